// round 6
// baseline (speedup 1.0000x reference)
#include <cuda_runtime.h>
#include <cuda_bf16.h>

// ---------------- Problem constants ----------------
#define Bn    64
#define Tn    256
#define Cn    256
#define Hn    8
#define HSn   32         // head size
#define Ln    6
#define Vn    96
#define NROWS (Bn*Tn)    // 16384
#define CC    (Cn*Cn)    // 65536
#define EPSF  1e-5f

// ---------------- Scratch (static device memory; no allocation) ----------------
// 5 activation buffers of [NROWS, Cn] + nll[NROWS]
__device__ float g_scratch[5 * NROWS * Cn + NROWS];

// ---------------- Embedding: x = tok_emb[idx] + pos_emb[t] ----------------
__global__ void embed_kernel(const int* __restrict__ idx,
                             const float* __restrict__ tok,
                             const float* __restrict__ pos,
                             float* __restrict__ x) {
    int row = blockIdx.x;          // b*T + t
    int c = threadIdx.x;
    int token = idx[row];
    x[row * Cn + c] = tok[token * Cn + c] + pos[(row & (Tn - 1)) * Cn + c];
}

// ---------------- SGEMM: Cout[M,Nd] = A[M,K] @ W[K,Nd] (+bias)(+relu) ----------------
#define BM 128
#define BN 64
#define BK 16

__global__ __launch_bounds__(256) void gemm_kernel(
    const float* __restrict__ A, const float* __restrict__ W,
    const float* __restrict__ bias, float* __restrict__ Cout,
    int M, int Nd, int K, int relu)
{
    __shared__ float As[BK][BM];
    __shared__ float Bs[BK][BN];

    int tid = threadIdx.x;
    int tx = tid & 15;    // N direction (0..15)
    int ty = tid >> 4;    // M direction (0..15)
    int aRowBase = blockIdx.y * BM;
    int bColBase = blockIdx.x * BN;

    float acc[8][4] = {};

    for (int kt = 0; kt < K; kt += BK) {
        // Load A tile: 128x16 = 512 float4, 2 per thread, store transposed
        #pragma unroll
        for (int i = 0; i < 2; i++) {
            int f = tid + i * 256;
            int row = f >> 2;            // 0..127
            int c4 = (f & 3) << 2;       // 0,4,8,12
            float4 v = *(const float4*)(A + (size_t)(aRowBase + row) * K + kt + c4);
            As[c4 + 0][row] = v.x;
            As[c4 + 1][row] = v.y;
            As[c4 + 2][row] = v.z;
            As[c4 + 3][row] = v.w;
        }
        // Load B tile: 16x64 = 256 float4, 1 per thread
        {
            int row = tid >> 4;              // 0..15
            int c4 = (tid & 15) << 2;        // 0..60
            int col = bColBase + c4;
            float4 v = make_float4(0.f, 0.f, 0.f, 0.f);
            if (col < Nd)
                v = *(const float4*)(W + (size_t)(kt + row) * Nd + col);
            *(float4*)&Bs[row][c4] = v;
        }
        __syncthreads();

        #pragma unroll
        for (int k = 0; k < BK; k++) {
            float rm[8], rn[4];
            #pragma unroll
            for (int i = 0; i < 8; i++) rm[i] = As[k][ty * 8 + i];
            #pragma unroll
            for (int j = 0; j < 4; j++) rn[j] = Bs[k][tx * 4 + j];
            #pragma unroll
            for (int i = 0; i < 8; i++)
                #pragma unroll
                for (int j = 0; j < 4; j++)
                    acc[i][j] += rm[i] * rn[j];
        }
        __syncthreads();
    }

    #pragma unroll
    for (int i = 0; i < 8; i++) {
        int row = aRowBase + ty * 8 + i;
        #pragma unroll
        for (int j = 0; j < 4; j++) {
            int col = bColBase + tx * 4 + j;
            if (col < Nd) {
                float v = acc[i][j];
                if (bias) v += bias[col];
                if (relu) v = fmaxf(v, 0.f);
                Cout[(size_t)row * Nd + col] = v;
            }
        }
    }
}

// ---------------- Fused causal attention ----------------
// Block per (head, batch); thread t = query row. K/V staged in smem in 2 chunks
// of 128 keys (32KB static smem). Online softmax, scale = C^-0.5 = 1/16.
__global__ __launch_bounds__(256) void attn_kernel(
    const float* __restrict__ Q, const float* __restrict__ K,
    const float* __restrict__ V, float* __restrict__ O)
{
    __shared__ float Ks[128 * HSn];
    __shared__ float Vs[128 * HSn];

    int h = blockIdx.x;
    int b = blockIdx.y;
    int t = threadIdx.x;
    size_t base = (size_t)(b * Tn) * Cn + h * HSn;

    // load my query row into registers
    float q[HSn];
    {
        const float4* qp = (const float4*)(Q + base + (size_t)t * Cn);
        #pragma unroll
        for (int i = 0; i < 8; i++) {
            float4 f = qp[i];
            q[4*i+0] = f.x; q[4*i+1] = f.y; q[4*i+2] = f.z; q[4*i+3] = f.w;
        }
    }

    float m = -1e30f, l = 0.f;
    float out[HSn];
    #pragma unroll
    for (int i = 0; i < HSn; i++) out[i] = 0.f;

    #pragma unroll
    for (int ch = 0; ch < 2; ch++) {
        __syncthreads();   // protect previous chunk's reads
        // stage 128 keys/values: 128*8 float4 per tensor, 4 per thread
        const float* Kg = K + base + (size_t)(ch * 128) * Cn;
        const float* Vg = V + base + (size_t)(ch * 128) * Cn;
        #pragma unroll
        for (int i = threadIdx.x; i < 128 * 8; i += 256) {
            int row = i >> 3;
            int c4 = (i & 7) << 2;
            ((float4*)Ks)[i] = *(const float4*)(Kg + (size_t)row * Cn + c4);
            ((float4*)Vs)[i] = *(const float4*)(Vg + (size_t)row * Cn + c4);
        }
        __syncthreads();

        int jend = t - ch * 128;            // causal bound within chunk
        if (jend > 127) jend = 127;
        for (int j = 0; j <= jend; j++) {
            const float4* kr = (const float4*)(Ks + j * HSn);
            float s = 0.f;
            #pragma unroll
            for (int i = 0; i < 8; i++) {
                float4 kk = kr[i];
                s += q[4*i+0]*kk.x + q[4*i+1]*kk.y + q[4*i+2]*kk.z + q[4*i+3]*kk.w;
            }
            s *= 0.0625f;                    // C^-0.5 = 1/16
            float mn = fmaxf(m, s);
            float al = __expf(m - mn);
            float p  = __expf(s - mn);
            l = l * al + p;
            const float4* vr = (const float4*)(Vs + j * HSn);
            #pragma unroll
            for (int i = 0; i < 8; i++) {
                float4 vv = vr[i];
                out[4*i+0] = out[4*i+0]*al + p*vv.x;
                out[4*i+1] = out[4*i+1]*al + p*vv.y;
                out[4*i+2] = out[4*i+2]*al + p*vv.z;
                out[4*i+3] = out[4*i+3]*al + p*vv.w;
            }
            m = mn;
        }
    }

    float inv = 1.f / l;
    float4* op = (float4*)(O + base + (size_t)t * Cn);
    #pragma unroll
    for (int i = 0; i < 8; i++) {
        float4 o;
        o.x = out[4*i+0]*inv; o.y = out[4*i+1]*inv;
        o.z = out[4*i+2]*inv; o.w = out[4*i+3]*inv;
        op[i] = o;
    }
}

// ---------------- Residual add + LayerNorm (in-place on x). t==nullptr => plain LN ----------------
__global__ __launch_bounds__(256) void add_ln_kernel(
    float* __restrict__ x, const float* __restrict__ t,
    const float* __restrict__ w, const float* __restrict__ bb)
{
    int row = blockIdx.x;
    int c = threadIdx.x;
    float v = x[(size_t)row * Cn + c];
    if (t) v += t[(size_t)row * Cn + c];

    float s = v, s2 = v * v;
    #pragma unroll
    for (int o = 16; o; o >>= 1) {
        s  += __shfl_xor_sync(0xFFFFFFFFu, s, o);
        s2 += __shfl_xor_sync(0xFFFFFFFFu, s2, o);
    }
    __shared__ float sh[16];
    int warp = c >> 5, lane = c & 31;
    if (lane == 0) { sh[warp] = s; sh[warp + 8] = s2; }
    __syncthreads();
    float sum = 0.f, sum2 = 0.f;
    #pragma unroll
    for (int i = 0; i < 8; i++) { sum += sh[i]; sum2 += sh[i + 8]; }

    float mean = sum * (1.f / Cn);
    float var  = sum2 * (1.f / Cn) - mean * mean;
    float r = rsqrtf(var + EPSF);
    x[(size_t)row * Cn + c] = (v - mean) * r * w[c] + bb[c];
}

// ---------------- Loss: per-row NLL (warp per row), then deterministic mean ----------------
__global__ __launch_bounds__(256) void loss_row_kernel(
    const float* __restrict__ logits, const int* __restrict__ target,
    float* __restrict__ nll)
{
    int gwarp = (blockIdx.x * blockDim.x + threadIdx.x) >> 5;
    int lane = threadIdx.x & 31;
    if (gwarp >= NROWS) return;
    const float* lg = logits + (size_t)gwarp * Vn;
    float v0 = lg[lane], v1 = lg[lane + 32], v2 = lg[lane + 64];
    float mx = fmaxf(v0, fmaxf(v1, v2));
    #pragma unroll
    for (int o = 16; o; o >>= 1) mx = fmaxf(mx, __shfl_xor_sync(0xFFFFFFFFu, mx, o));
    float s = __expf(v0 - mx) + __expf(v1 - mx) + __expf(v2 - mx);
    #pragma unroll
    for (int o = 16; o; o >>= 1) s += __shfl_xor_sync(0xFFFFFFFFu, s, o);
    if (lane == 0) {
        float lse = mx + logf(s);
        nll[gwarp] = lse - lg[target[gwarp]];
    }
}

__global__ __launch_bounds__(256) void loss_reduce_kernel(
    const float* __restrict__ nll, float* __restrict__ out)
{
    __shared__ float sh[256];
    float s = 0.f;
    for (int i = threadIdx.x; i < NROWS; i += 256) s += nll[i];
    sh[threadIdx.x] = s;
    __syncthreads();
    for (int st = 128; st; st >>= 1) {
        if (threadIdx.x < st) sh[threadIdx.x] += sh[threadIdx.x + st];
        __syncthreads();
    }
    if (threadIdx.x == 0) out[0] = sh[0] * (1.f / NROWS);
}

// ---------------- Host-side launch sequence (graph-capturable) ----------------
extern "C" void kernel_launch(void* const* d_in, const int* in_sizes, int n_in,
                              void* d_out, int out_size) {
    const int*   idx    = (const int*)  d_in[0];
    const int*   target = (const int*)  d_in[1];
    const float* tok    = (const float*)d_in[2];
    const float* pos    = (const float*)d_in[3];
    const float* Wq     = (const float*)d_in[4];
    const float* Wk     = (const float*)d_in[5];
    const float* Wv     = (const float*)d_in[6];
    const float* Wo     = (const float*)d_in[7];
    const float* bo     = (const float*)d_in[8];
    const float* W1     = (const float*)d_in[9];
    const float* b1     = (const float*)d_in[10];
    const float* W2     = (const float*)d_in[11];
    const float* b2     = (const float*)d_in[12];
    const float* ln1w   = (const float*)d_in[13];
    const float* ln1b   = (const float*)d_in[14];
    const float* ln2w   = (const float*)d_in[15];
    const float* ln2b   = (const float*)d_in[16];
    const float* lnfw   = (const float*)d_in[17];
    const float* lnfb   = (const float*)d_in[18];
    const float* Wlm    = (const float*)d_in[19];
    const float* blm    = (const float*)d_in[20];

    float* logits = (float*)d_out;

    float* s = nullptr;
    cudaGetSymbolAddress((void**)&s, g_scratch);
    float* x   = s;
    float* ba  = s + 1 * (size_t)NROWS * Cn;
    float* bb  = s + 2 * (size_t)NROWS * Cn;
    float* bc  = s + 3 * (size_t)NROWS * Cn;
    float* bd  = s + 4 * (size_t)NROWS * Cn;
    float* nll = s + 5 * (size_t)NROWS * Cn;

    dim3 gemmGridC((Cn + BN - 1) / BN, NROWS / BM);   // (4, 128)
    dim3 gemmGridV((Vn + BN - 1) / BN, NROWS / BM);   // (2, 128)

    embed_kernel<<<NROWS, 256>>>(idx, tok, pos, x);

    for (int l = 0; l < Ln; l++) {
        const float* wq = Wq + (size_t)l * CC;
        const float* wk = Wk + (size_t)l * CC;
        const float* wv = Wv + (size_t)l * CC;
        const float* wo = Wo + (size_t)l * CC;
        const float* w1 = W1 + (size_t)l * CC;
        const float* w2 = W2 + (size_t)l * CC;

        gemm_kernel<<<gemmGridC, 256>>>(x, wq, nullptr, ba, NROWS, Cn, Cn, 0);
        gemm_kernel<<<gemmGridC, 256>>>(x, wk, nullptr, bb, NROWS, Cn, Cn, 0);
        gemm_kernel<<<gemmGridC, 256>>>(x, wv, nullptr, bc, NROWS, Cn, Cn, 0);

        attn_kernel<<<dim3(Hn, Bn), 256>>>(ba, bb, bc, bd);

        gemm_kernel<<<gemmGridC, 256>>>(bd, wo, bo + (size_t)l * Cn, ba, NROWS, Cn, Cn, 0);
        add_ln_kernel<<<NROWS, 256>>>(x, ba, ln1w + (size_t)l * Cn, ln1b + (size_t)l * Cn);

        gemm_kernel<<<gemmGridC, 256>>>(x, w1, b1 + (size_t)l * Cn, bb, NROWS, Cn, Cn, 1);
        gemm_kernel<<<gemmGridC, 256>>>(bb, w2, b2 + (size_t)l * Cn, bc, NROWS, Cn, Cn, 0);
        add_ln_kernel<<<NROWS, 256>>>(x, bc, ln2w + (size_t)l * Cn, ln2b + (size_t)l * Cn);
    }

    // final LN (in place), then LM head straight into d_out
    add_ln_kernel<<<NROWS, 256>>>(x, nullptr, lnfw, lnfb);
    gemm_kernel<<<gemmGridV, 256>>>(x, Wlm, blm, logits, NROWS, Vn, Cn, 0);

    // loss (if the output buffer includes it)
    if (out_size > NROWS * Vn) {
        loss_row_kernel<<<NROWS / 8, 256>>>(logits, target, nll);
        loss_reduce_kernel<<<1, 256>>>(nll, logits + (size_t)NROWS * Vn);
    }
}

// round 7
// speedup vs baseline: 1.6912x; 1.6912x over previous
#include <cuda_runtime.h>
#include <cuda_bf16.h>

// ---------------- Problem constants ----------------
#define Bn    64
#define Tn    256
#define Cn    256
#define Hn    8
#define HSn   32         // head size
#define Ln    6
#define Vn    96
#define NROWS (Bn*Tn)    // 16384
#define CC    (Cn*Cn)    // 65536
#define EPSF  1e-5f
#define KK    256        // K dim of every GEMM

// ---------------- Scratch (static device memory; no allocation) ----------------
__device__ float g_scratch[5 * NROWS * Cn + NROWS];

// ---------------- Embedding: x = tok_emb[idx] + pos_emb[t] ----------------
__global__ void embed_kernel(const int* __restrict__ idx,
                             const float* __restrict__ tok,
                             const float* __restrict__ pos,
                             float* __restrict__ x) {
    int row = blockIdx.x;
    int c = threadIdx.x;
    int token = idx[row];
    x[row * Cn + c] = tok[token * Cn + c] + pos[(row & (Tn - 1)) * Cn + c];
}

// ---------------- tf32 helpers ----------------
__device__ __forceinline__ unsigned f2tf(float f) {
    unsigned u;
    asm("cvt.rna.tf32.f32 %0, %1;" : "=r"(u) : "f"(f));
    return u;
}

__device__ __forceinline__ void mma_tf32(float* d, const unsigned* a, const unsigned* b) {
    asm volatile("mma.sync.aligned.m16n8k8.row.col.f32.tf32.tf32.f32 "
        "{%0,%1,%2,%3}, {%4,%5,%6,%7}, {%8,%9}, {%0,%1,%2,%3};"
        : "+f"(d[0]), "+f"(d[1]), "+f"(d[2]), "+f"(d[3])
        : "r"(a[0]), "r"(a[1]), "r"(a[2]), "r"(a[3]), "r"(b[0]), "r"(b[1]));
}

// ---------------- Tensor-core tf32 GEMM ----------------
// Cout[M,Nd] = A[M,256] @ W[256,Nd] (+bias)(+relu), fp32 accumulate.
// CTA: 128(M) x 64(N), BK=32. 8 warps (4 M x 2 N), warp tile 32x32.
// Conflict-free smem: A stride 36 (bank = 4m+k), B stride 68 (bank = 4k+n).
#define ASTR 36
#define BSTR 68

__global__ __launch_bounds__(256, 2) void gemm_tc_kernel(
    const float* __restrict__ A, const float* __restrict__ W,
    const float* __restrict__ bias, float* __restrict__ Cout,
    int Nd, int relu)
{
    __shared__ unsigned As[128 * ASTR];   // 18432 B
    __shared__ unsigned Bs[32 * BSTR];    //  8704 B

    int tid = threadIdx.x;
    int lane = tid & 31;
    int warp = tid >> 5;
    int g = lane >> 2, t = lane & 3;
    int wm = (warp & 3) * 32;     // warp M offset within CTA tile
    int wn = (warp >> 2) * 32;    // warp N offset within CTA tile
    int aRowBase = blockIdx.y * 128;
    int bColBase = blockIdx.x * 64;

    float acc[2][4][4] = {};

    float4 ar[4];
    float4 br[2];

    // prologue: prefetch K-chunk 0 into registers
    #pragma unroll
    for (int i = 0; i < 4; i++) {
        int fi = tid + i * 256;
        int r = fi >> 3, c = (fi & 7) << 2;
        ar[i] = *(const float4*)(A + (size_t)(aRowBase + r) * KK + c);
    }
    #pragma unroll
    for (int i = 0; i < 2; i++) {
        int fi = tid + i * 256;
        int r = fi >> 4, c = (fi & 15) << 2;
        int col = bColBase + c;
        br[i] = (col < Nd) ? *(const float4*)(W + (size_t)r * Nd + col)
                           : make_float4(0.f, 0.f, 0.f, 0.f);
    }

    for (int kt = 0; kt < 8; kt++) {
        __syncthreads();   // previous chunk's compute done -> smem reusable
        // store prefetched chunk to smem, converting to tf32
        #pragma unroll
        for (int i = 0; i < 4; i++) {
            int fi = tid + i * 256;
            int r = fi >> 3, c = (fi & 7) << 2;
            uint4 u;
            u.x = f2tf(ar[i].x); u.y = f2tf(ar[i].y);
            u.z = f2tf(ar[i].z); u.w = f2tf(ar[i].w);
            *(uint4*)&As[r * ASTR + c] = u;
        }
        #pragma unroll
        for (int i = 0; i < 2; i++) {
            int fi = tid + i * 256;
            int r = fi >> 4, c = (fi & 15) << 2;
            uint4 u;
            u.x = f2tf(br[i].x); u.y = f2tf(br[i].y);
            u.z = f2tf(br[i].z); u.w = f2tf(br[i].w);
            *(uint4*)&Bs[r * BSTR + c] = u;
        }
        __syncthreads();

        // prefetch next chunk (global latency overlaps the mma loop below)
        if (kt < 7) {
            int kn = (kt + 1) * 32;
            #pragma unroll
            for (int i = 0; i < 4; i++) {
                int fi = tid + i * 256;
                int r = fi >> 3, c = (fi & 7) << 2;
                ar[i] = *(const float4*)(A + (size_t)(aRowBase + r) * KK + kn + c);
            }
            #pragma unroll
            for (int i = 0; i < 2; i++) {
                int fi = tid + i * 256;
                int r = fi >> 4, c = (fi & 15) << 2;
                int col = bColBase + c;
                br[i] = (col < Nd) ? *(const float4*)(W + (size_t)(kn + r) * Nd + col)
                                   : make_float4(0.f, 0.f, 0.f, 0.f);
            }
        }

        // 4 k-steps of m16n8k8
        #pragma unroll
        for (int ks = 0; ks < 4; ks++) {
            int kb = ks * 8;
            unsigned af[2][4], bf[4][2];
            #pragma unroll
            for (int i = 0; i < 2; i++) {
                int rb = wm + i * 16;
                af[i][0] = As[(rb + g) * ASTR + kb + t];
                af[i][1] = As[(rb + g + 8) * ASTR + kb + t];
                af[i][2] = As[(rb + g) * ASTR + kb + t + 4];
                af[i][3] = As[(rb + g + 8) * ASTR + kb + t + 4];
            }
            #pragma unroll
            for (int j = 0; j < 4; j++) {
                int cb = wn + j * 8 + g;
                bf[j][0] = Bs[(kb + t) * BSTR + cb];
                bf[j][1] = Bs[(kb + t + 4) * BSTR + cb];
            }
            #pragma unroll
            for (int i = 0; i < 2; i++)
                #pragma unroll
                for (int j = 0; j < 4; j++)
                    mma_tf32(acc[i][j], af[i], bf[j]);
        }
    }

    // epilogue: bias + relu + store (float2 per fragment row)
    #pragma unroll
    for (int i = 0; i < 2; i++) {
        #pragma unroll
        for (int j = 0; j < 4; j++) {
            int col = bColBase + wn + j * 8 + t * 2;
            if (col >= Nd) continue;
            float bx = 0.f, by = 0.f;
            if (bias) { bx = bias[col]; by = bias[col + 1]; }
            int r0 = aRowBase + wm + i * 16 + g;
            float v0 = acc[i][j][0] + bx, v1 = acc[i][j][1] + by;
            float v2 = acc[i][j][2] + bx, v3 = acc[i][j][3] + by;
            if (relu) {
                v0 = fmaxf(v0, 0.f); v1 = fmaxf(v1, 0.f);
                v2 = fmaxf(v2, 0.f); v3 = fmaxf(v3, 0.f);
            }
            *(float2*)&Cout[(size_t)r0 * Nd + col]       = make_float2(v0, v1);
            *(float2*)&Cout[(size_t)(r0 + 8) * Nd + col] = make_float2(v2, v3);
        }
    }
}

// ---------------- Fused causal attention (fp32, unchanged from R5) ----------------
__global__ __launch_bounds__(256) void attn_kernel(
    const float* __restrict__ Q, const float* __restrict__ K,
    const float* __restrict__ V, float* __restrict__ O)
{
    __shared__ float Ks[128 * HSn];
    __shared__ float Vs[128 * HSn];

    int h = blockIdx.x;
    int b = blockIdx.y;
    int t = threadIdx.x;
    size_t base = (size_t)(b * Tn) * Cn + h * HSn;

    float q[HSn];
    {
        const float4* qp = (const float4*)(Q + base + (size_t)t * Cn);
        #pragma unroll
        for (int i = 0; i < 8; i++) {
            float4 f = qp[i];
            q[4*i+0] = f.x; q[4*i+1] = f.y; q[4*i+2] = f.z; q[4*i+3] = f.w;
        }
    }

    float m = -1e30f, l = 0.f;
    float out[HSn];
    #pragma unroll
    for (int i = 0; i < HSn; i++) out[i] = 0.f;

    #pragma unroll
    for (int ch = 0; ch < 2; ch++) {
        __syncthreads();
        const float* Kg = K + base + (size_t)(ch * 128) * Cn;
        const float* Vg = V + base + (size_t)(ch * 128) * Cn;
        #pragma unroll
        for (int i = threadIdx.x; i < 128 * 8; i += 256) {
            int row = i >> 3;
            int c4 = (i & 7) << 2;
            ((float4*)Ks)[i] = *(const float4*)(Kg + (size_t)row * Cn + c4);
            ((float4*)Vs)[i] = *(const float4*)(Vg + (size_t)row * Cn + c4);
        }
        __syncthreads();

        int jend = t - ch * 128;
        if (jend > 127) jend = 127;
        for (int j = 0; j <= jend; j++) {
            const float4* kr = (const float4*)(Ks + j * HSn);
            float s = 0.f;
            #pragma unroll
            for (int i = 0; i < 8; i++) {
                float4 kk = kr[i];
                s += q[4*i+0]*kk.x + q[4*i+1]*kk.y + q[4*i+2]*kk.z + q[4*i+3]*kk.w;
            }
            s *= 0.0625f;
            float mn = fmaxf(m, s);
            float al = __expf(m - mn);
            float p  = __expf(s - mn);
            l = l * al + p;
            const float4* vr = (const float4*)(Vs + j * HSn);
            #pragma unroll
            for (int i = 0; i < 8; i++) {
                float4 vv = vr[i];
                out[4*i+0] = out[4*i+0]*al + p*vv.x;
                out[4*i+1] = out[4*i+1]*al + p*vv.y;
                out[4*i+2] = out[4*i+2]*al + p*vv.z;
                out[4*i+3] = out[4*i+3]*al + p*vv.w;
            }
            m = mn;
        }
    }

    float inv = 1.f / l;
    float4* op = (float4*)(O + base + (size_t)t * Cn);
    #pragma unroll
    for (int i = 0; i < 8; i++) {
        float4 o;
        o.x = out[4*i+0]*inv; o.y = out[4*i+1]*inv;
        o.z = out[4*i+2]*inv; o.w = out[4*i+3]*inv;
        op[i] = o;
    }
}

// ---------------- Residual add + LayerNorm (in-place). t==nullptr => plain LN ----------------
__global__ __launch_bounds__(256) void add_ln_kernel(
    float* __restrict__ x, const float* __restrict__ t,
    const float* __restrict__ w, const float* __restrict__ bb)
{
    int row = blockIdx.x;
    int c = threadIdx.x;
    float v = x[(size_t)row * Cn + c];
    if (t) v += t[(size_t)row * Cn + c];

    float s = v, s2 = v * v;
    #pragma unroll
    for (int o = 16; o; o >>= 1) {
        s  += __shfl_xor_sync(0xFFFFFFFFu, s, o);
        s2 += __shfl_xor_sync(0xFFFFFFFFu, s2, o);
    }
    __shared__ float sh[16];
    int warp = c >> 5, lane = c & 31;
    if (lane == 0) { sh[warp] = s; sh[warp + 8] = s2; }
    __syncthreads();
    float sum = 0.f, sum2 = 0.f;
    #pragma unroll
    for (int i = 0; i < 8; i++) { sum += sh[i]; sum2 += sh[i + 8]; }

    float mean = sum * (1.f / Cn);
    float var  = sum2 * (1.f / Cn) - mean * mean;
    float r = rsqrtf(var + EPSF);
    x[(size_t)row * Cn + c] = (v - mean) * r * w[c] + bb[c];
}

// ---------------- Loss ----------------
__global__ __launch_bounds__(256) void loss_row_kernel(
    const float* __restrict__ logits, const int* __restrict__ target,
    float* __restrict__ nll)
{
    int gwarp = (blockIdx.x * blockDim.x + threadIdx.x) >> 5;
    int lane = threadIdx.x & 31;
    if (gwarp >= NROWS) return;
    const float* lg = logits + (size_t)gwarp * Vn;
    float v0 = lg[lane], v1 = lg[lane + 32], v2 = lg[lane + 64];
    float mx = fmaxf(v0, fmaxf(v1, v2));
    #pragma unroll
    for (int o = 16; o; o >>= 1) mx = fmaxf(mx, __shfl_xor_sync(0xFFFFFFFFu, mx, o));
    float s = __expf(v0 - mx) + __expf(v1 - mx) + __expf(v2 - mx);
    #pragma unroll
    for (int o = 16; o; o >>= 1) s += __shfl_xor_sync(0xFFFFFFFFu, s, o);
    if (lane == 0) {
        float lse = mx + logf(s);
        nll[gwarp] = lse - lg[target[gwarp]];
    }
}

__global__ __launch_bounds__(256) void loss_reduce_kernel(
    const float* __restrict__ nll, float* __restrict__ out)
{
    __shared__ float sh[256];
    float s = 0.f;
    for (int i = threadIdx.x; i < NROWS; i += 256) s += nll[i];
    sh[threadIdx.x] = s;
    __syncthreads();
    for (int st = 128; st; st >>= 1) {
        if (threadIdx.x < st) sh[threadIdx.x] += sh[threadIdx.x + st];
        __syncthreads();
    }
    if (threadIdx.x == 0) out[0] = sh[0] * (1.f / NROWS);
}

// ---------------- Host-side launch sequence (graph-capturable) ----------------
extern "C" void kernel_launch(void* const* d_in, const int* in_sizes, int n_in,
                              void* d_out, int out_size) {
    const int*   idx    = (const int*)  d_in[0];
    const int*   target = (const int*)  d_in[1];
    const float* tok    = (const float*)d_in[2];
    const float* pos    = (const float*)d_in[3];
    const float* Wq     = (const float*)d_in[4];
    const float* Wk     = (const float*)d_in[5];
    const float* Wv     = (const float*)d_in[6];
    const float* Wo     = (const float*)d_in[7];
    const float* bo     = (const float*)d_in[8];
    const float* W1     = (const float*)d_in[9];
    const float* b1     = (const float*)d_in[10];
    const float* W2     = (const float*)d_in[11];
    const float* b2     = (const float*)d_in[12];
    const float* ln1w   = (const float*)d_in[13];
    const float* ln1b   = (const float*)d_in[14];
    const float* ln2w   = (const float*)d_in[15];
    const float* ln2b   = (const float*)d_in[16];
    const float* lnfw   = (const float*)d_in[17];
    const float* lnfb   = (const float*)d_in[18];
    const float* Wlm    = (const float*)d_in[19];
    const float* blm    = (const float*)d_in[20];

    float* logits = (float*)d_out;

    float* s = nullptr;
    cudaGetSymbolAddress((void**)&s, g_scratch);
    float* x   = s;
    float* ba  = s + 1 * (size_t)NROWS * Cn;
    float* bb  = s + 2 * (size_t)NROWS * Cn;
    float* bc  = s + 3 * (size_t)NROWS * Cn;
    float* bd  = s + 4 * (size_t)NROWS * Cn;
    float* nll = s + 5 * (size_t)NROWS * Cn;

    dim3 gemmGridC(Cn / 64, NROWS / 128);          // (4, 128)
    dim3 gemmGridV((Vn + 63) / 64, NROWS / 128);   // (2, 128)

    embed_kernel<<<NROWS, 256>>>(idx, tok, pos, x);

    for (int l = 0; l < Ln; l++) {
        const float* wq = Wq + (size_t)l * CC;
        const float* wk = Wk + (size_t)l * CC;
        const float* wv = Wv + (size_t)l * CC;
        const float* wo = Wo + (size_t)l * CC;
        const float* w1 = W1 + (size_t)l * CC;
        const float* w2 = W2 + (size_t)l * CC;

        gemm_tc_kernel<<<gemmGridC, 256>>>(x, wq, nullptr, ba, Cn, 0);
        gemm_tc_kernel<<<gemmGridC, 256>>>(x, wk, nullptr, bb, Cn, 0);
        gemm_tc_kernel<<<gemmGridC, 256>>>(x, wv, nullptr, bc, Cn, 0);

        attn_kernel<<<dim3(Hn, Bn), 256>>>(ba, bb, bc, bd);

        gemm_tc_kernel<<<gemmGridC, 256>>>(bd, wo, bo + (size_t)l * Cn, ba, Cn, 0);
        add_ln_kernel<<<NROWS, 256>>>(x, ba, ln1w + (size_t)l * Cn, ln1b + (size_t)l * Cn);

        gemm_tc_kernel<<<gemmGridC, 256>>>(x, w1, b1 + (size_t)l * Cn, bb, Cn, 1);
        gemm_tc_kernel<<<gemmGridC, 256>>>(bb, w2, b2 + (size_t)l * Cn, bc, Cn, 0);
        add_ln_kernel<<<NROWS, 256>>>(x, bc, ln2w + (size_t)l * Cn, ln2b + (size_t)l * Cn);
    }

    add_ln_kernel<<<NROWS, 256>>>(x, nullptr, lnfw, lnfb);
    gemm_tc_kernel<<<gemmGridV, 256>>>(x, Wlm, blm, logits, Vn, 0);

    if (out_size > NROWS * Vn) {
        loss_row_kernel<<<NROWS / 8, 256>>>(logits, target, nll);
        loss_reduce_kernel<<<1, 256>>>(nll, logits + (size_t)NROWS * Vn);
    }
}

// round 8
// speedup vs baseline: 2.5658x; 1.5172x over previous
#include <cuda_runtime.h>
#include <cuda_bf16.h>

// ---------------- Problem constants ----------------
#define Bn    64
#define Tn    256
#define Cn    256
#define Hn    8
#define HSn   32         // head size
#define Ln    6
#define Vn    96
#define NROWS (Bn*Tn)    // 16384
#define CC    (Cn*Cn)    // 65536
#define EPSF  1e-5f
#define KK    256        // K dim of every GEMM

// ---------------- Scratch (static device memory; no allocation) ----------------
__device__ float g_scratch[5 * NROWS * Cn + NROWS];

// ---------------- Embedding ----------------
__global__ void embed_kernel(const int* __restrict__ idx,
                             const float* __restrict__ tok,
                             const float* __restrict__ pos,
                             float* __restrict__ x) {
    int row = blockIdx.x;
    int c = threadIdx.x;
    int token = idx[row];
    x[row * Cn + c] = tok[token * Cn + c] + pos[(row & (Tn - 1)) * Cn + c];
}

// ---------------- tf32 helpers ----------------
__device__ __forceinline__ unsigned f2tf(float f) {
    unsigned u;
    asm("cvt.rna.tf32.f32 %0, %1;" : "=r"(u) : "f"(f));
    return u;
}

__device__ __forceinline__ void mma_tf32(float* d, const unsigned* a, const unsigned* b) {
    asm volatile("mma.sync.aligned.m16n8k8.row.col.f32.tf32.tf32.f32 "
        "{%0,%1,%2,%3}, {%4,%5,%6,%7}, {%8,%9}, {%0,%1,%2,%3};"
        : "+f"(d[0]), "+f"(d[1]), "+f"(d[2]), "+f"(d[3])
        : "r"(a[0]), "r"(a[1]), "r"(a[2]), "r"(a[3]), "r"(b[0]), "r"(b[1]));
}

// ---------------- Tensor-core tf32 GEMM (double-buffered) ----------------
// Cout[M,Nd] = A[M,256] @ W[256,Nd] (+bias)(+relu). CTA 128x64, BK=32,
// 8 warps (4M x 2N), warp tile 32x32.
// transT: write output transposed as [B][C][T] (for the K projection).
#define ASTR 36
#define BSTR 72
#define A_BUF (128*ASTR)   // 4608 u
#define B_BUF (32*BSTR)    // 2304 u
#define GSMEM ((2*A_BUF + 2*B_BUF) * 4)   // 55296 bytes

__global__ __launch_bounds__(256, 2) void gemm_tc_kernel(
    const float* __restrict__ A, const float* __restrict__ W,
    const float* __restrict__ bias, float* __restrict__ Cout,
    int Nd, int relu, int transT)
{
    extern __shared__ unsigned gsm[];

    int tid = threadIdx.x;
    int lane = tid & 31;
    int warp = tid >> 5;
    int g = lane >> 2, t = lane & 3;
    int wm = (warp & 3) * 32;
    int wn = (warp >> 2) * 32;
    int aRowBase = blockIdx.y * 128;
    int bColBase = blockIdx.x * 64;

    float acc[2][4][4] = {};
    float4 ar[4];
    float4 br[2];

    // prologue: prefetch chunk 0
    #pragma unroll
    for (int i = 0; i < 4; i++) {
        int fi = tid + i * 256;
        int r = fi >> 3, c = (fi & 7) << 2;
        ar[i] = *(const float4*)(A + (size_t)(aRowBase + r) * KK + c);
    }
    #pragma unroll
    for (int i = 0; i < 2; i++) {
        int fi = tid + i * 256;
        int r = fi >> 4, c = (fi & 15) << 2;
        int col = bColBase + c;
        br[i] = (col < Nd) ? *(const float4*)(W + (size_t)r * Nd + col)
                           : make_float4(0.f, 0.f, 0.f, 0.f);
    }
    // store chunk 0 to buffer 0
    {
        unsigned* As = gsm;
        unsigned* Bs = gsm + 2 * A_BUF;
        #pragma unroll
        for (int i = 0; i < 4; i++) {
            int fi = tid + i * 256;
            int r = fi >> 3, c = (fi & 7) << 2;
            uint4 u = { f2tf(ar[i].x), f2tf(ar[i].y), f2tf(ar[i].z), f2tf(ar[i].w) };
            *(uint4*)&As[r * ASTR + c] = u;
        }
        #pragma unroll
        for (int i = 0; i < 2; i++) {
            int fi = tid + i * 256;
            int r = fi >> 4, c = (fi & 15) << 2;
            uint4 u = { f2tf(br[i].x), f2tf(br[i].y), f2tf(br[i].z), f2tf(br[i].w) };
            *(uint4*)&Bs[r * BSTR + c] = u;
        }
    }
    __syncthreads();

    for (int kt = 0; kt < 8; kt++) {
        int cur = kt & 1;
        unsigned* As = gsm + cur * A_BUF;
        unsigned* Bs = gsm + 2 * A_BUF + cur * B_BUF;

        // prefetch next chunk (global), overlaps with compute below
        if (kt < 7) {
            int kn = (kt + 1) * 32;
            #pragma unroll
            for (int i = 0; i < 4; i++) {
                int fi = tid + i * 256;
                int r = fi >> 3, c = (fi & 7) << 2;
                ar[i] = *(const float4*)(A + (size_t)(aRowBase + r) * KK + kn + c);
            }
            #pragma unroll
            for (int i = 0; i < 2; i++) {
                int fi = tid + i * 256;
                int r = fi >> 4, c = (fi & 15) << 2;
                int col = bColBase + c;
                br[i] = (col < Nd) ? *(const float4*)(W + (size_t)(kn + r) * Nd + col)
                                   : make_float4(0.f, 0.f, 0.f, 0.f);
            }
        }

        // compute on current buffer: 4 k-steps of m16n8k8
        #pragma unroll
        for (int ks = 0; ks < 4; ks++) {
            int kb = ks * 8;
            unsigned af[2][4], bf[4][2];
            #pragma unroll
            for (int i = 0; i < 2; i++) {
                int rb = wm + i * 16;
                af[i][0] = As[(rb + g) * ASTR + kb + t];
                af[i][1] = As[(rb + g + 8) * ASTR + kb + t];
                af[i][2] = As[(rb + g) * ASTR + kb + t + 4];
                af[i][3] = As[(rb + g + 8) * ASTR + kb + t + 4];
            }
            #pragma unroll
            for (int j = 0; j < 4; j++) {
                int cb = wn + j * 8 + g;
                bf[j][0] = Bs[(kb + t) * BSTR + cb];
                bf[j][1] = Bs[(kb + t + 4) * BSTR + cb];
            }
            #pragma unroll
            for (int i = 0; i < 2; i++)
                #pragma unroll
                for (int j = 0; j < 4; j++)
                    mma_tf32(acc[i][j], af[i], bf[j]);
        }

        // store prefetched chunk into the other buffer
        if (kt < 7) {
            unsigned* Asn = gsm + (1 - cur) * A_BUF;
            unsigned* Bsn = gsm + 2 * A_BUF + (1 - cur) * B_BUF;
            #pragma unroll
            for (int i = 0; i < 4; i++) {
                int fi = tid + i * 256;
                int r = fi >> 3, c = (fi & 7) << 2;
                uint4 u = { f2tf(ar[i].x), f2tf(ar[i].y), f2tf(ar[i].z), f2tf(ar[i].w) };
                *(uint4*)&Asn[r * ASTR + c] = u;
            }
            #pragma unroll
            for (int i = 0; i < 2; i++) {
                int fi = tid + i * 256;
                int r = fi >> 4, c = (fi & 15) << 2;
                uint4 u = { f2tf(br[i].x), f2tf(br[i].y), f2tf(br[i].z), f2tf(br[i].w) };
                *(uint4*)&Bsn[r * BSTR + c] = u;
            }
        }
        __syncthreads();
    }

    if (!transT) {
        // normal epilogue
        #pragma unroll
        for (int i = 0; i < 2; i++) {
            #pragma unroll
            for (int j = 0; j < 4; j++) {
                int col = bColBase + wn + j * 8 + t * 2;
                if (col >= Nd) continue;
                float bx = 0.f, by = 0.f;
                if (bias) { bx = bias[col]; by = bias[col + 1]; }
                int r0 = aRowBase + wm + i * 16 + g;
                float v0 = acc[i][j][0] + bx, v1 = acc[i][j][1] + by;
                float v2 = acc[i][j][2] + bx, v3 = acc[i][j][3] + by;
                if (relu) {
                    v0 = fmaxf(v0, 0.f); v1 = fmaxf(v1, 0.f);
                    v2 = fmaxf(v2, 0.f); v3 = fmaxf(v3, 0.f);
                }
                *(float2*)&Cout[(size_t)r0 * Nd + col]       = make_float2(v0, v1);
                *(float2*)&Cout[(size_t)(r0 + 8) * Nd + col] = make_float2(v2, v3);
            }
        }
    } else {
        // transposed epilogue: out[b][c][t], per-warp smem transpose patch
        float* patch = (float*)gsm + warp * 1056;   // 32 cols x 32 rows, stride 33
        #pragma unroll
        for (int i = 0; i < 2; i++) {
            #pragma unroll
            for (int j = 0; j < 4; j++) {
                int c0 = j * 8 + t * 2;
                int r0 = i * 16 + g;
                patch[(c0    ) * 33 + r0    ] = acc[i][j][0];
                patch[(c0 + 1) * 33 + r0    ] = acc[i][j][1];
                patch[(c0    ) * 33 + r0 + 8] = acc[i][j][2];
                patch[(c0 + 1) * 33 + r0 + 8] = acc[i][j][3];
            }
        }
        __syncwarp();
        int rowG = aRowBase + wm;
        int bIdx = rowG >> 8;
        int tg = (lane & 7) * 4;
        int chi = lane >> 3;
        int tBase = (rowG & 255) + tg;
        #pragma unroll
        for (int jj = 0; jj < 8; jj++) {
            int c = jj * 4 + chi;
            float4 v;
            v.x = patch[c * 33 + tg + 0];
            v.y = patch[c * 33 + tg + 1];
            v.z = patch[c * 33 + tg + 2];
            v.w = patch[c * 33 + tg + 3];
            *(float4*)&Cout[(size_t)bIdx * (Cn * Tn) +
                            (size_t)(bColBase + wn + c) * Tn + tBase] = v;
        }
    }
}

// ---------------- Tensor-core flash attention ----------------
// Grid (4 qblocks, Hn, Bn), 128 threads (4 warps). Warp owns 16 query rows.
// K pre-transposed in KT[B][C][T]; keys processed in 64-chunks.
#define KSTR 72
#define VSTR 40
#define PSTR 68

__global__ __launch_bounds__(128, 4) void attn_tc_kernel(
    const float* __restrict__ Q,    // [B*T, C]
    const float* __restrict__ KT,   // [B][C][T]
    const float* __restrict__ V,    // [B*T, C]
    float* __restrict__ O)          // [B*T, C]
{
    __shared__ unsigned Ks[32 * KSTR];
    __shared__ unsigned Vs[64 * VSTR];
    __shared__ unsigned Ps[4][16 * PSTR];

    int qb = 3 - blockIdx.x;          // heavy blocks first
    int h  = blockIdx.y;
    int b  = blockIdx.z;
    int tid = threadIdx.x;
    int warp = tid >> 5, lane = tid & 31;
    int g = lane >> 2, t = lane & 3;
    int hsoff = h * HSn;
    int q0 = qb * 64;
    int qrow = q0 + warp * 16;

    // Q fragments (pre-scaled by C^-0.5 = 1/16), resident in registers
    unsigned qa[4][4];
    {
        const float* Qb = Q + (size_t)(b * Tn + qrow) * Cn + hsoff;
        #pragma unroll
        for (int ks = 0; ks < 4; ks++) {
            qa[ks][0] = f2tf(Qb[(size_t)g       * Cn + ks * 8 + t    ] * 0.0625f);
            qa[ks][1] = f2tf(Qb[(size_t)(g + 8) * Cn + ks * 8 + t    ] * 0.0625f);
            qa[ks][2] = f2tf(Qb[(size_t)g       * Cn + ks * 8 + t + 4] * 0.0625f);
            qa[ks][3] = f2tf(Qb[(size_t)(g + 8) * Cn + ks * 8 + t + 4] * 0.0625f);
        }
    }

    float oa[4][4] = {};              // out accum [16 x 32]
    float m0 = -1e30f, m1 = -1e30f, l0 = 0.f, l1 = 0.f;

    const float* KTb = KT + (size_t)b * (Cn * Tn) + (size_t)hsoff * Tn;
    const float* Vb  = V  + (size_t)(b * Tn) * Cn + hsoff;
    unsigned* Pw = Ps[warp];

    for (int kc = 0; kc <= qb; kc++) {
        __syncthreads();
        // K^T chunk [32 hs][64 keys], converted to tf32
        #pragma unroll
        for (int i = 0; i < 4; i++) {
            int fi = tid + i * 128;
            int r = fi >> 4, c4 = (fi & 15) << 2;
            float4 v = *(const float4*)(KTb + (size_t)r * Tn + kc * 64 + c4);
            uint4 u = { f2tf(v.x), f2tf(v.y), f2tf(v.z), f2tf(v.w) };
            *(uint4*)&Ks[r * KSTR + c4] = u;
        }
        // V chunk [64 keys][32 hs]
        #pragma unroll
        for (int i = 0; i < 4; i++) {
            int fi = tid + i * 128;
            int r = fi >> 3, c4 = (fi & 7) << 2;
            float4 v = *(const float4*)(Vb + (size_t)(kc * 64 + r) * Cn + c4);
            uint4 u = { f2tf(v.x), f2tf(v.y), f2tf(v.z), f2tf(v.w) };
            *(uint4*)&Vs[r * VSTR + c4] = u;
        }
        __syncthreads();

        // S = Q @ K^T : [16 x 64]
        float sc[8][4];
        #pragma unroll
        for (int nf = 0; nf < 8; nf++)
            #pragma unroll
            for (int j = 0; j < 4; j++) sc[nf][j] = 0.f;
        #pragma unroll
        for (int ks = 0; ks < 4; ks++) {
            #pragma unroll
            for (int nf = 0; nf < 8; nf++) {
                unsigned bf[2];
                bf[0] = Ks[(ks * 8 + t    ) * KSTR + nf * 8 + g];
                bf[1] = Ks[(ks * 8 + t + 4) * KSTR + nf * 8 + g];
                mma_tf32(sc[nf], qa[ks], bf);
            }
        }

        // causal mask on diagonal chunk
        if (kc == qb) {
            int r0 = warp * 16 + g;
            #pragma unroll
            for (int nf = 0; nf < 8; nf++) {
                int c0 = nf * 8 + 2 * t;
                if (c0     > r0    ) sc[nf][0] = -1e30f;
                if (c0 + 1 > r0    ) sc[nf][1] = -1e30f;
                if (c0     > r0 + 8) sc[nf][2] = -1e30f;
                if (c0 + 1 > r0 + 8) sc[nf][3] = -1e30f;
            }
        }

        // online softmax: row maxima (rows g, g+8)
        float mx0 = -1e30f, mx1 = -1e30f;
        #pragma unroll
        for (int nf = 0; nf < 8; nf++) {
            mx0 = fmaxf(mx0, fmaxf(sc[nf][0], sc[nf][1]));
            mx1 = fmaxf(mx1, fmaxf(sc[nf][2], sc[nf][3]));
        }
        #pragma unroll
        for (int o = 1; o <= 2; o <<= 1) {
            mx0 = fmaxf(mx0, __shfl_xor_sync(0xFFFFFFFFu, mx0, o));
            mx1 = fmaxf(mx1, __shfl_xor_sync(0xFFFFFFFFu, mx1, o));
        }
        float nm0 = fmaxf(m0, mx0), nm1 = fmaxf(m1, mx1);
        float al0 = __expf(m0 - nm0), al1 = __expf(m1 - nm1);

        float s0 = 0.f, s1 = 0.f;
        #pragma unroll
        for (int nf = 0; nf < 8; nf++) {
            float p0 = __expf(sc[nf][0] - nm0);
            float p1 = __expf(sc[nf][1] - nm0);
            float p2 = __expf(sc[nf][2] - nm1);
            float p3 = __expf(sc[nf][3] - nm1);
            s0 += p0 + p1; s1 += p2 + p3;
            uint2 u01 = make_uint2(f2tf(p0), f2tf(p1));
            uint2 u23 = make_uint2(f2tf(p2), f2tf(p3));
            *(uint2*)&Pw[(g    ) * PSTR + nf * 8 + 2 * t] = u01;
            *(uint2*)&Pw[(g + 8) * PSTR + nf * 8 + 2 * t] = u23;
        }
        #pragma unroll
        for (int o = 1; o <= 2; o <<= 1) {
            s0 += __shfl_xor_sync(0xFFFFFFFFu, s0, o);
            s1 += __shfl_xor_sync(0xFFFFFFFFu, s1, o);
        }
        l0 = l0 * al0 + s0;
        l1 = l1 * al1 + s1;
        m0 = nm0; m1 = nm1;

        // rescale accumulator
        #pragma unroll
        for (int nf = 0; nf < 4; nf++) {
            oa[nf][0] *= al0; oa[nf][1] *= al0;
            oa[nf][2] *= al1; oa[nf][3] *= al1;
        }
        __syncwarp();

        // out += P @ V : [16 x 64] @ [64 x 32]
        #pragma unroll
        for (int ks = 0; ks < 8; ks++) {
            unsigned pa[4];
            pa[0] = Pw[(g    ) * PSTR + ks * 8 + t    ];
            pa[1] = Pw[(g + 8) * PSTR + ks * 8 + t    ];
            pa[2] = Pw[(g    ) * PSTR + ks * 8 + t + 4];
            pa[3] = Pw[(g + 8) * PSTR + ks * 8 + t + 4];
            #pragma unroll
            for (int nf = 0; nf < 4; nf++) {
                unsigned vb[2];
                vb[0] = Vs[(ks * 8 + t    ) * VSTR + nf * 8 + g];
                vb[1] = Vs[(ks * 8 + t + 4) * VSTR + nf * 8 + g];
                mma_tf32(oa[nf], pa, vb);
            }
        }
    }

    // write normalized output
    float i0 = 1.f / l0, i1 = 1.f / l1;
    float* Ob = O + (size_t)(b * Tn + qrow) * Cn + hsoff;
    #pragma unroll
    for (int nf = 0; nf < 4; nf++) {
        int c = nf * 8 + 2 * t;
        *(float2*)&Ob[(size_t)g       * Cn + c] = make_float2(oa[nf][0] * i0, oa[nf][1] * i0);
        *(float2*)&Ob[(size_t)(g + 8) * Cn + c] = make_float2(oa[nf][2] * i1, oa[nf][3] * i1);
    }
}

// ---------------- Residual add + LayerNorm ----------------
__global__ __launch_bounds__(256) void add_ln_kernel(
    float* __restrict__ x, const float* __restrict__ t,
    const float* __restrict__ w, const float* __restrict__ bb)
{
    int row = blockIdx.x;
    int c = threadIdx.x;
    float v = x[(size_t)row * Cn + c];
    if (t) v += t[(size_t)row * Cn + c];

    float s = v, s2 = v * v;
    #pragma unroll
    for (int o = 16; o; o >>= 1) {
        s  += __shfl_xor_sync(0xFFFFFFFFu, s, o);
        s2 += __shfl_xor_sync(0xFFFFFFFFu, s2, o);
    }
    __shared__ float sh[16];
    int warp = c >> 5, lane = c & 31;
    if (lane == 0) { sh[warp] = s; sh[warp + 8] = s2; }
    __syncthreads();
    float sum = 0.f, sum2 = 0.f;
    #pragma unroll
    for (int i = 0; i < 8; i++) { sum += sh[i]; sum2 += sh[i + 8]; }

    float mean = sum * (1.f / Cn);
    float var  = sum2 * (1.f / Cn) - mean * mean;
    float r = rsqrtf(var + EPSF);
    x[(size_t)row * Cn + c] = (v - mean) * r * w[c] + bb[c];
}

// ---------------- Loss ----------------
__global__ __launch_bounds__(256) void loss_row_kernel(
    const float* __restrict__ logits, const int* __restrict__ target,
    float* __restrict__ nll)
{
    int gwarp = (blockIdx.x * blockDim.x + threadIdx.x) >> 5;
    int lane = threadIdx.x & 31;
    if (gwarp >= NROWS) return;
    const float* lg = logits + (size_t)gwarp * Vn;
    float v0 = lg[lane], v1 = lg[lane + 32], v2 = lg[lane + 64];
    float mx = fmaxf(v0, fmaxf(v1, v2));
    #pragma unroll
    for (int o = 16; o; o >>= 1) mx = fmaxf(mx, __shfl_xor_sync(0xFFFFFFFFu, mx, o));
    float s = __expf(v0 - mx) + __expf(v1 - mx) + __expf(v2 - mx);
    #pragma unroll
    for (int o = 16; o; o >>= 1) s += __shfl_xor_sync(0xFFFFFFFFu, s, o);
    if (lane == 0) {
        float lse = mx + logf(s);
        nll[gwarp] = lse - lg[target[gwarp]];
    }
}

__global__ __launch_bounds__(256) void loss_reduce_kernel(
    const float* __restrict__ nll, float* __restrict__ out)
{
    __shared__ float sh[256];
    float s = 0.f;
    for (int i = threadIdx.x; i < NROWS; i += 256) s += nll[i];
    sh[threadIdx.x] = s;
    __syncthreads();
    for (int st = 128; st; st >>= 1) {
        if (threadIdx.x < st) sh[threadIdx.x] += sh[threadIdx.x + st];
        __syncthreads();
    }
    if (threadIdx.x == 0) out[0] = sh[0] * (1.f / NROWS);
}

// ---------------- Host-side launch sequence (graph-capturable) ----------------
extern "C" void kernel_launch(void* const* d_in, const int* in_sizes, int n_in,
                              void* d_out, int out_size) {
    const int*   idx    = (const int*)  d_in[0];
    const int*   target = (const int*)  d_in[1];
    const float* tok    = (const float*)d_in[2];
    const float* pos    = (const float*)d_in[3];
    const float* Wq     = (const float*)d_in[4];
    const float* Wk     = (const float*)d_in[5];
    const float* Wv     = (const float*)d_in[6];
    const float* Wo     = (const float*)d_in[7];
    const float* bo     = (const float*)d_in[8];
    const float* W1     = (const float*)d_in[9];
    const float* b1     = (const float*)d_in[10];
    const float* W2     = (const float*)d_in[11];
    const float* b2     = (const float*)d_in[12];
    const float* ln1w   = (const float*)d_in[13];
    const float* ln1b   = (const float*)d_in[14];
    const float* ln2w   = (const float*)d_in[15];
    const float* ln2b   = (const float*)d_in[16];
    const float* lnfw   = (const float*)d_in[17];
    const float* lnfb   = (const float*)d_in[18];
    const float* Wlm    = (const float*)d_in[19];
    const float* blm    = (const float*)d_in[20];

    float* logits = (float*)d_out;

    float* s = nullptr;
    cudaGetSymbolAddress((void**)&s, g_scratch);
    float* x   = s;
    float* ba  = s + 1 * (size_t)NROWS * Cn;
    float* bb  = s + 2 * (size_t)NROWS * Cn;   // K^T lives here
    float* bc  = s + 3 * (size_t)NROWS * Cn;
    float* bd  = s + 4 * (size_t)NROWS * Cn;
    float* nll = s + 5 * (size_t)NROWS * Cn;

    cudaFuncSetAttribute(gemm_tc_kernel,
                         cudaFuncAttributeMaxDynamicSharedMemorySize, GSMEM);

    dim3 gemmGridC(Cn / 64, NROWS / 128);          // (4, 128)
    dim3 gemmGridV((Vn + 63) / 64, NROWS / 128);   // (2, 128)
    dim3 attnGrid(4, Hn, Bn);

    embed_kernel<<<NROWS, 256>>>(idx, tok, pos, x);

    for (int l = 0; l < Ln; l++) {
        const float* wq = Wq + (size_t)l * CC;
        const float* wk = Wk + (size_t)l * CC;
        const float* wv = Wv + (size_t)l * CC;
        const float* wo = Wo + (size_t)l * CC;
        const float* w1 = W1 + (size_t)l * CC;
        const float* w2 = W2 + (size_t)l * CC;

        gemm_tc_kernel<<<gemmGridC, 256, GSMEM>>>(x, wq, nullptr, ba, Cn, 0, 0);
        gemm_tc_kernel<<<gemmGridC, 256, GSMEM>>>(x, wk, nullptr, bb, Cn, 0, 1); // K^T
        gemm_tc_kernel<<<gemmGridC, 256, GSMEM>>>(x, wv, nullptr, bc, Cn, 0, 0);

        attn_tc_kernel<<<attnGrid, 128>>>(ba, bb, bc, bd);

        gemm_tc_kernel<<<gemmGridC, 256, GSMEM>>>(bd, wo, bo + (size_t)l * Cn, ba, Cn, 0, 0);
        add_ln_kernel<<<NROWS, 256>>>(x, ba, ln1w + (size_t)l * Cn, ln1b + (size_t)l * Cn);

        gemm_tc_kernel<<<gemmGridC, 256, GSMEM>>>(x, w1, b1 + (size_t)l * Cn, bb, Cn, 1, 0);
        gemm_tc_kernel<<<gemmGridC, 256, GSMEM>>>(bb, w2, b2 + (size_t)l * Cn, bc, Cn, 0, 0);
        add_ln_kernel<<<NROWS, 256>>>(x, bc, ln2w + (size_t)l * Cn, ln2b + (size_t)l * Cn);
    }

    add_ln_kernel<<<NROWS, 256>>>(x, nullptr, lnfw, lnfb);
    gemm_tc_kernel<<<gemmGridV, 256, GSMEM>>>(x, Wlm, blm, logits, Vn, 0, 0);

    if (out_size > NROWS * Vn) {
        loss_row_kernel<<<NROWS / 8, 256>>>(logits, target, nll);
        loss_reduce_kernel<<<1, 256>>>(nll, logits + (size_t)NROWS * Vn);
    }
}